// round 6
// baseline (speedup 1.0000x reference)
#include <cuda_runtime.h>
#include <stdint.h>

// LSTM: H=50, input 1, T=1024, B independent batch elements.
// One block (224 threads) per batch element. COLUMN-SPLIT R=2 layout:
//   thread j<100  : rows (j, j+100), columns [0,28)   (even half)
//   thread 100+j  : rows (j, j+100), columns [28,56)  (odd half, cols>=50 pad 0)
// Weight regs per thread = 2 rows x 28 cols = 56 (same as R1), but each
// broadcast LDS.128 of h feeds 4 FFMA2 (ratio 1:3.7 vs R1's 1:2).
// Partial sums -> shared; threads k<50 combine halves, activate all 4 gates,
// update c (private) and h_sh. Two __syncthreads per step, single h buffer.
// Gate order (PyTorch): i[0:50], f[50:100], g[100:150], o[150:200].

#define HH 50
#define TT 1024
#define BT 224

typedef unsigned long long ull;

__device__ __forceinline__ float sigf(float x) {
    return 1.0f / (1.0f + __expf(-x));
}
__device__ __forceinline__ float tanhfast(float x) {
    return fmaf(2.0f, sigf(2.0f * x), -1.0f);   // tanh via 2*sig(2x)-1
}
__device__ __forceinline__ void fma2(ull& d, ull a, ull b) {
    asm("fma.rn.f32x2 %0, %1, %2, %0;" : "+l"(d) : "l"(a), "l"(b));
}
__device__ __forceinline__ ull pack2(float lo, float hi) {
    return ((ull)__float_as_uint(hi) << 32) | (ull)__float_as_uint(lo);
}
__device__ __forceinline__ float sum2(ull a) {
    return __uint_as_float((unsigned)a) + __uint_as_float((unsigned)(a >> 32));
}

__global__ void __launch_bounds__(BT, 4)
lstm_kernel(const float* __restrict__ x,      // [B, T, 1]
            const float* __restrict__ W_ih,   // [200, 1]
            const float* __restrict__ W_hh,   // [200, 50]
            const float* __restrict__ b_ih,   // [200]
            const float* __restrict__ b_hh,   // [200]
            const float* __restrict__ W_lin,  // [1, 50]
            const float* __restrict__ b_lin,  // [1]
            float* __restrict__ out)          // [B, 1]
{
    __shared__ __align__(16) float h_sh[56];    // h padded; [50..55] stay 0
    __shared__ float ps_sh[2][200];             // partial sums per half
    __shared__ float x_sh[TT];

    const int j = threadIdx.x;
    const int b = blockIdx.x;
    const bool p1   = (j < 200);
    const int  half = (j < 100) ? 0 : 1;
    const int  rA   = p1 ? (j - half * 100) : 0;   // 0..99
    const int  rB   = rA + 100;
    const int  c0   = half * 28;                   // column base

    for (int i = j; i < TT; i += BT) x_sh[i] = x[(size_t)b * TT + i];
    if (j < 56) h_sh[j] = 0.0f;                    // h0 = 0; pad stays 0

    // Weights: rows rA,rB over cols [c0, c0+28). Cols >= 50 are zero pads.
    ull wpA[14], wpB[14];
    float baseA = 0.0f, baseB = 0.0f, wihA = 0.0f, wihB = 0.0f;
    if (p1) {
        #pragma unroll
        for (int q = 0; q < 14; q++) {
            const int col = c0 + 2 * q;
            float a0 = (col     < HH) ? W_hh[rA * HH + col]     : 0.0f;
            float a1 = (col + 1 < HH) ? W_hh[rA * HH + col + 1] : 0.0f;
            float v0 = (col     < HH) ? W_hh[rB * HH + col]     : 0.0f;
            float v1 = (col + 1 < HH) ? W_hh[rB * HH + col + 1] : 0.0f;
            wpA[q] = pack2(a0, a1);
            wpB[q] = pack2(v0, v1);
        }
        if (half == 0) {   // bias + x*W_ih carried by even half only
            baseA = b_ih[rA] + b_hh[rA];  wihA = W_ih[rA];
            baseB = b_ih[rB] + b_hh[rB];  wihB = W_ih[rB];
        }
    }
    float c = 0.0f;                                // owned by threads j<50
    __syncthreads();

    #pragma unroll 1
    for (int t = 0; t < TT; t++) {
        if (p1) {
            const float xt = x_sh[t];
            ull aA = 0ull, aB = 0ull;
            const ulonglong2* h2 = (const ulonglong2*)(h_sh + c0);
            #pragma unroll
            for (int q = 0; q < 7; q++) {
                ulonglong2 hv = h2[q];             // broadcast LDS.128
                fma2(aA, wpA[2 * q],     hv.x);
                fma2(aA, wpA[2 * q + 1], hv.y);
                fma2(aB, wpB[2 * q],     hv.x);
                fma2(aB, wpB[2 * q + 1], hv.y);
            }
            ps_sh[half][rA] = sum2(aA) + fmaf(xt, wihA, baseA);
            ps_sh[half][rB] = sum2(aB) + fmaf(xt, wihB, baseB);
        }
        __syncthreads();
        if (j < HH) {
            const float si = ps_sh[0][j]       + ps_sh[1][j];
            const float sf = ps_sh[0][j +  50] + ps_sh[1][j +  50];
            const float sg = ps_sh[0][j + 100] + ps_sh[1][j + 100];
            const float so = ps_sh[0][j + 150] + ps_sh[1][j + 150];
            const float gi = sigf(si);
            const float gf = sigf(sf);
            const float gg = tanhfast(sg);
            const float go = sigf(so);
            c = fmaf(gf, c, gi * gg);
            h_sh[j] = go * tanhfast(c);
        }
        __syncthreads();
    }

    if (j == 0) {
        float s = b_lin[0];
        #pragma unroll 1
        for (int q = 0; q < HH; q++) s = fmaf(h_sh[q], W_lin[q], s);
        out[b] = s;
    }
}

extern "C" void kernel_launch(void* const* d_in, const int* in_sizes, int n_in,
                              void* d_out, int out_size) {
    const float* x     = (const float*)d_in[0];
    const float* W_ih  = (const float*)d_in[1];
    const float* W_hh  = (const float*)d_in[2];
    const float* b_ih  = (const float*)d_in[3];
    const float* b_hh  = (const float*)d_in[4];
    const float* W_lin = (const float*)d_in[5];
    const float* b_lin = (const float*)d_in[6];
    float* out = (float*)d_out;

    int B = in_sizes[0] / TT;
    lstm_kernel<<<B, BT>>>(x, W_ih, W_hh, b_ih, b_hh, W_lin, b_lin, out);
}